// round 5
// baseline (speedup 1.0000x reference)
#include <cuda_runtime.h>
#include <cstdint>
#include <cstddef>

// out[t, n*16+f] = relu(bias[f] + sum_{j=0..31} x[t-2j-1, n] * w_pn[j][f])
// w_pn = per-filter l2-normalized relu(weights); rows t-2j-1 < 0 contribute 0.
//
// Block: 32 n-cols x 32 t-rows x all 16 f. 256 threads = 8 warps.
// Stage x transposed into smem (sx[n][t], 96-row strip incl. 63-row history,
// row stride 98 floats == 2 mod 32 -> conflict-free LDS.64 across 32 lanes).
// Thread tile: 1 n x 16 t x 4 f, t-PACKED f32x2 accumulators so the x operand
// {x[r], x[r+1]} is one aligned LDS.64 (no dup movs). Weights pre-duplicated
// {w,w} in smem, broadcast LDS.64, amortized over 8 t-pairs.
// LDS bytes/lane-FFMA2 = (4*8 + 8)/32 = 1.25B < 2B crossbar budget -> FMA-bound.

#define T_DIM 2048
#define N_DIM 4096
#define L_DIM 32
#define F_DIM 16
#define OUTW  (N_DIM * F_DIM)

#define ROWS   96            // staged strip rows (t0-63 .. t0+31, padded to 96)
#define RSTRIDE 98           // floats per sx row; 98 % 32 == 2 -> conflict-free
#define RSTRIDE_U 49         // ull per sx row

using ull = unsigned long long;

__device__ __forceinline__ ull dup2(float v) {
    ull r;
    unsigned u = __float_as_uint(v);
    asm("mov.b64 %0, {%1, %1};" : "=l"(r) : "r"(u));
    return r;
}

__device__ __forceinline__ void fma2(ull& d, ull a, ull b) {
    asm("fma.rn.f32x2 %0, %1, %2, %0;" : "+l"(d) : "l"(a), "l"(b));
}

__device__ __forceinline__ float2 unpack2(ull v) {
    float2 r;
    asm("mov.b64 {%0, %1}, %2;" : "=f"(r.x), "=f"(r.y) : "l"(v));
    return r;
}

__global__ void __launch_bounds__(256, 2)
tlayer_kernel(const float* __restrict__ x,
              const float* __restrict__ Wg,
              const float* __restrict__ Bg,
              float* __restrict__ out)
{
    __shared__ __align__(16) float sx[32 * RSTRIDE];   // transposed x strip
    __shared__ __align__(8)  ull   swdup[L_DIM * F_DIM]; // {w,w} per (j,f)
    __shared__ __align__(8)  ull   sbdup[F_DIM];         // {b,b} per f

    const int tid  = threadIdx.x;
    const int lane = tid & 31;
    const int warp = tid >> 5;

    const int n0    = blockIdx.x * 32;
    const int t0    = blockIdx.y * 32;
    const int tbase = t0 - 63;          // lowest row needed: t0 - 2*31 - 1

    // ---- weight prep: relu + per-filter l2 normalize, store duplicated ----
    if (tid < F_DIM) {
        float ss = 0.0f;
        for (int j = 0; j < L_DIM; ++j) {
            float wv = fmaxf(__ldg(Wg + j * F_DIM + tid), 0.0f);
            ss += wv * wv;
        }
        float inv = rsqrtf(fmaxf(ss, 1e-12f));
        for (int j = 0; j < L_DIM; ++j) {
            float wn = fmaxf(__ldg(Wg + j * F_DIM + tid), 0.0f) * inv;
            swdup[j * F_DIM + tid] = dup2(wn);
        }
        sbdup[tid] = dup2(__ldg(Bg + tid));
    }

    // ---- stage x strip, transposed: sx[n-lane][row i] = x[tbase+i][n0+lane]
    // warp w handles rows i = w, w+8, ..., 12 coalesced 128B LDG per warp.
#pragma unroll
    for (int k = 0; k < 12; ++k) {
        int i = warp + k * 8;
        int g = tbase + i;
        float v = 0.0f;
        if (g >= 0 && g < T_DIM) v = __ldg(x + (size_t)g * N_DIM + n0 + lane);
        sx[lane * RSTRIDE + i] = v;
    }
    __syncthreads();

    // ---- compute: warp -> (tg in [0,2): 16 t, fg in [0,4): 4 f) ----
    const int tg = warp >> 2;
    const int fg = warp & 3;

    const ull* xrow = reinterpret_cast<const ull*>(sx) + lane * RSTRIDE_U;
    // ull index of x-pair for t-pair p at lag j:
    //   ((t0 + tg*16 + 2p) - 2j - 1 - tbase)/2 = tg*8 + 31 + p - j
    const int base = tg * 8 + 31;

    ull acc[8][4];
#pragma unroll
    for (int ff = 0; ff < 4; ++ff) {
        ull b = sbdup[fg * 4 + ff];
#pragma unroll
        for (int p = 0; p < 8; ++p) acc[p][ff] = b;
    }

    // sliding window of 8 x-pair ulls; invariant: W[(p - j) & 7] = xrow[base + p - j]
    ull W[8];
#pragma unroll
    for (int p = 0; p < 8; ++p) W[p] = xrow[base + p];

#pragma unroll
    for (int j = 0; j < L_DIM; ++j) {
        ull w0 = swdup[j * F_DIM + fg * 4 + 0];
        ull w1 = swdup[j * F_DIM + fg * 4 + 1];
        ull w2 = swdup[j * F_DIM + fg * 4 + 2];
        ull w3 = swdup[j * F_DIM + fg * 4 + 3];
#pragma unroll
        for (int p = 0; p < 8; ++p) {
            ull xv = W[(p - j + 64) & 7];
            fma2(acc[p][0], xv, w0);
            fma2(acc[p][1], xv, w1);
            fma2(acc[p][2], xv, w2);
            fma2(acc[p][3], xv, w3);
        }
        if (j < L_DIM - 1) {
            // next iter's p=0 slot: xrow[base - j - 1]
            W[(-(j + 1) + 64) & 7] = xrow[base - j - 1];
        }
    }

    // ---- epilogue: transpose t-packed accs into f-contiguous float4 stores
    const size_t col = (size_t)(n0 + lane) * F_DIM + fg * 4;
#pragma unroll
    for (int p = 0; p < 8; ++p) {
        int t = t0 + tg * 16 + 2 * p;
        float2 a0 = unpack2(acc[p][0]);
        float2 a1 = unpack2(acc[p][1]);
        float2 a2 = unpack2(acc[p][2]);
        float2 a3 = unpack2(acc[p][3]);
        float4 v0, v1;
        v0.x = fmaxf(a0.x, 0.0f); v0.y = fmaxf(a1.x, 0.0f);
        v0.z = fmaxf(a2.x, 0.0f); v0.w = fmaxf(a3.x, 0.0f);
        v1.x = fmaxf(a0.y, 0.0f); v1.y = fmaxf(a1.y, 0.0f);
        v1.z = fmaxf(a2.y, 0.0f); v1.w = fmaxf(a3.y, 0.0f);
        *reinterpret_cast<float4*>(out + (size_t)t * OUTW + col)       = v0;
        *reinterpret_cast<float4*>(out + (size_t)(t + 1) * OUTW + col) = v1;
    }
}

extern "C" void kernel_launch(void* const* d_in, const int* in_sizes, int n_in,
                              void* d_out, int out_size) {
    (void)in_sizes; (void)n_in; (void)out_size;
    const float* x = (const float*)d_in[0];   // [2048, 4096]
    const float* W = (const float*)d_in[1];   // [32, 16]
    const float* B = (const float*)d_in[2];   // [16]
    float* out = (float*)d_out;               // [2048, 65536]

    dim3 grid(N_DIM / 32, T_DIM / 32);        // (128, 64)
    tlayer_kernel<<<grid, 256>>>(x, W, B, out);
}